// round 2
// baseline (speedup 1.0000x reference)
#include <cuda_runtime.h>

// FlowNetC correlation: out[b, (dy+4)*9+(dx+4), y, x] =
//   (1/C) * sum_c in1[b,c,y,x] * in2[b,c,y+dy,x+dx], zero-padded.
// Shapes: in1,in2 [8,256,96,128] f32; out [8,81,96,128] f32.

#define B_ 8
#define C_ 256
#define H_ 96
#define W_ 128
#define CC 8      // channel chunk
#define W2 136    // padded in2 row: x in [-4, 131]

__global__ __launch_bounds__(128) void corr_kernel(
    const float* __restrict__ in1,
    const float* __restrict__ in2,
    float* __restrict__ out)
{
    // Block: one dy (blockIdx.x in 0..8), 4 rows (blockIdx.y*4), batch b.
    // Thread: warp = row (ty), lane -> 4 consecutive x pixels.
    __shared__ float s2[CC][4][W2];   // in2 window, 16B-aligned rows (136*4 = 544 = 34*16)

    const int dyi  = blockIdx.x;        // 0..8
    const int y0   = blockIdx.y * 4;
    const int b    = blockIdx.z;
    const int tid  = threadIdx.x;
    const int ty   = tid >> 5;          // 0..3 (warp = row)
    const int lane = tid & 31;
    const int x0   = lane << 2;         // 0,4,...,124
    const int dyo  = dyi - 4;

    float acc[4][9];
#pragma unroll
    for (int i = 0; i < 4; i++)
#pragma unroll
        for (int d = 0; d < 9; d++) acc[i][d] = 0.0f;

    const float* in1p = in1 + (((long)b * C_) * H_ + (y0 + ty)) * W_ + x0;
    // per-channel stride in in1 for this thread:
    const long c_stride = (long)H_ * W_;

    for (int c0 = 0; c0 < C_; c0 += CC) {
        // ---- stage in2 window: CC channels x 4 rows x 136 cols (zero-padded) ----
#pragma unroll
        for (int k = 0; k < (CC * 4 * W2 + 127) / 128; k++) {
            int idx = tid + k * 128;
            if (idx < CC * 4 * W2) {
                int cc  = idx / (4 * W2);
                int rem = idx - cc * (4 * W2);
                int r   = rem / W2;
                int xx  = rem - r * W2;
                int y2  = y0 + r + dyo;
                int x   = xx - 4;
                float v = 0.0f;
                if ((unsigned)y2 < H_ && (unsigned)x < W_)
                    v = in2[(((long)b * C_ + (c0 + cc)) * H_ + y2) * W_ + x];
                s2[cc][r][xx] = v;
            }
        }
        __syncthreads();

        // ---- compute: per channel, 4 pixels x 9 dx FMAs ----
#pragma unroll
        for (int cc = 0; cc < CC; cc++) {
            float4 a = *reinterpret_cast<const float4*>(in1p + (c0 + cc) * c_stride);
            float4 w0 = *reinterpret_cast<const float4*>(&s2[cc][ty][x0]);
            float4 w1 = *reinterpret_cast<const float4*>(&s2[cc][ty][x0 + 4]);
            float4 w2 = *reinterpret_cast<const float4*>(&s2[cc][ty][x0 + 8]);
            float w[12] = {w0.x, w0.y, w0.z, w0.w,
                           w1.x, w1.y, w1.z, w1.w,
                           w2.x, w2.y, w2.z, w2.w};
            float av[4] = {a.x, a.y, a.z, a.w};
#pragma unroll
            for (int i = 0; i < 4; i++)
#pragma unroll
                for (int d = 0; d < 9; d++)
                    acc[i][d] = fmaf(av[i], w[i + d], acc[i][d]);
        }
        __syncthreads();
    }

    // ---- epilogue: 9 float4 stores ----
    const float scale = 1.0f / (float)C_;
#pragma unroll
    for (int d = 0; d < 9; d++) {
        int ch = dyi * 9 + d;   // (dy+4)*9 + (dx+4)
        float* o = out + ((((long)b * 81 + ch) * H_) + (y0 + ty)) * W_ + x0;
        float4 v = make_float4(acc[0][d] * scale, acc[1][d] * scale,
                               acc[2][d] * scale, acc[3][d] * scale);
        *reinterpret_cast<float4*>(o) = v;
    }
}

extern "C" void kernel_launch(void* const* d_in, const int* in_sizes, int n_in,
                              void* d_out, int out_size)
{
    const float* in1 = (const float*)d_in[0];
    const float* in2 = (const float*)d_in[1];
    float* out = (float*)d_out;

    dim3 grid(9, H_ / 4, B_);   // dy, y-tiles, batch
    dim3 block(128);
    corr_kernel<<<grid, block>>>(in1, in2, out);
}

// round 4
// speedup vs baseline: 2.1273x; 2.1273x over previous
#include <cuda_runtime.h>
#include <cstdint>

// FlowNetC correlation: out[b, (dy+4)*9+(dx+4), y, x] =
//   (1/C) * sum_c in1[b,c,y,x] * in2[b,c,y+dy,x+dx], zero-padded.
// Shapes: in1,in2 [8,256,96,128] f32; out [8,81,96,128] f32.

#define B_   8
#define C_   256
#define H_   96
#define W_   128
#define HW_  (H_ * W_)
#define CC   4      // channels per chunk
#define ROWS 8      // output rows per block (warp = row)
#define W2   136    // padded in2 row: xx = x + 4, x in [-4, 131]

__global__ __launch_bounds__(256, 3) void corr_kernel(
    const float* __restrict__ in1,
    const float* __restrict__ in2,
    float* __restrict__ out)
{
    // Double-buffered in2 window: [buf][cc][row][xx]
    __shared__ float s2[2][CC][ROWS][W2];   // 34816 B

    const int dyi  = blockIdx.x;        // 0..8
    const int y0   = blockIdx.y * ROWS;
    const int b    = blockIdx.z;
    const int tid  = threadIdx.x;
    const int wid  = tid >> 5;          // warp = row, 0..7
    const int lane = tid & 31;
    const int x0   = lane << 2;         // 0..124
    const int dyo  = dyi - 4;

    // Zero the left/right pads once (staging never touches xx<4 or xx>=132,
    // so these stay zero across all chunks and both buffers).
    if (tid < 2 * CC * ROWS) {
        float* row = &s2[0][0][0][0] + tid * W2;
#pragma unroll
        for (int j = 0; j < 4; j++) { row[j] = 0.0f; row[132 + j] = 0.0f; }
    }

    // Staging source: warp wid stages in2 row y0+wid+dyo for cc=0..CC-1.
    const int  y2    = y0 + wid + dyo;
    const bool valid = ((unsigned)y2 < (unsigned)H_);
    const float* st_src = in2 + ((long)b * C_) * HW_
                              + (long)(valid ? y2 : 0) * W_ + x0;
    const int srcsz = valid ? 16 : 0;   // cp.async src_size=0 -> zero-fill

    // in1 source for compute: row y0+wid, pixels x0..x0+3.
    const float* a_src = in1 + ((long)b * C_) * HW_ + (long)(y0 + wid) * W_ + x0;

    // SMEM byte address of this thread's staging slot in buffer 0.
    uint32_t s_base;
    {
        const void* p = &s2[0][0][wid][4 + x0];
        asm("{ .reg .u64 t; cvta.to.shared.u64 t, %1; cvt.u32.u64 %0, t; }"
            : "=r"(s_base) : "l"(p));
    }
    const uint32_t buf_stride = (uint32_t)(sizeof(float) * CC * ROWS * W2);
    const uint32_t cc_stride  = (uint32_t)(sizeof(float) * ROWS * W2);

    // ---- prologue: stage chunk 0 into buffer 0 ----
#pragma unroll
    for (int cc = 0; cc < CC; cc++) {
        asm volatile("cp.async.cg.shared.global [%0], [%1], 16, %2;"
                     :: "r"(s_base + cc * cc_stride),
                        "l"(st_src + (long)cc * HW_),
                        "r"(srcsz) : "memory");
    }
    asm volatile("cp.async.commit_group;" ::: "memory");
    asm volatile("cp.async.wait_group 0;" ::: "memory");
    __syncthreads();

    float acc[4][9];
#pragma unroll
    for (int i = 0; i < 4; i++)
#pragma unroll
        for (int d = 0; d < 9; d++) acc[i][d] = 0.0f;

    int buf = 0;
    const float* a_run  = a_src;
    const float* st_run = st_src + (long)CC * HW_;

    for (int c0 = 0; c0 < C_; c0 += CC) {
        const bool has_next = (c0 + CC < C_);

        // Issue async staging of the NEXT chunk into the other buffer.
        if (has_next) {
            uint32_t dbase = s_base + (uint32_t)(buf ^ 1) * buf_stride;
#pragma unroll
            for (int cc = 0; cc < CC; cc++) {
                asm volatile("cp.async.cg.shared.global [%0], [%1], 16, %2;"
                             :: "r"(dbase + cc * cc_stride),
                                "l"(st_run + (long)cc * HW_),
                                "r"(srcsz) : "memory");
            }
            asm volatile("cp.async.commit_group;" ::: "memory");
        }

        // Compute on the current buffer (overlaps the async copies above).
        const float* srow = &s2[buf][0][wid][x0];
#pragma unroll
        for (int cc = 0; cc < CC; cc++) {
            float4 a  = *reinterpret_cast<const float4*>(a_run + (long)cc * HW_);
            const float* sr = srow + cc * (ROWS * W2);
            float4 w0 = *reinterpret_cast<const float4*>(sr);
            float4 w1 = *reinterpret_cast<const float4*>(sr + 4);
            float4 w2 = *reinterpret_cast<const float4*>(sr + 8);
            float w[12] = {w0.x, w0.y, w0.z, w0.w,
                           w1.x, w1.y, w1.z, w1.w,
                           w2.x, w2.y, w2.z, w2.w};
            float av[4] = {a.x, a.y, a.z, a.w};
#pragma unroll
            for (int i = 0; i < 4; i++)
#pragma unroll
                for (int d = 0; d < 9; d++)
                    acc[i][d] = fmaf(av[i], w[i + d], acc[i][d]);
        }

        if (has_next)
            asm volatile("cp.async.wait_group 0;" ::: "memory");
        __syncthreads();
        buf ^= 1;
        a_run  += (long)CC * HW_;
        st_run += (long)CC * HW_;
    }

    // ---- epilogue: 9 float4 stores per thread ----
    const float sc = 1.0f / (float)C_;
    float* ob = out + (((long)b * 81 + dyi * 9) * H_ + (y0 + wid)) * (long)W_ + x0;
#pragma unroll
    for (int d = 0; d < 9; d++) {
        float4 v = make_float4(acc[0][d] * sc, acc[1][d] * sc,
                               acc[2][d] * sc, acc[3][d] * sc);
        *reinterpret_cast<float4*>(ob + (long)d * HW_) = v;
    }
}

extern "C" void kernel_launch(void* const* d_in, const int* in_sizes, int n_in,
                              void* d_out, int out_size)
{
    const float* in1 = (const float*)d_in[0];
    const float* in2 = (const float*)d_in[1];
    float* out = (float*)d_out;

    dim3 grid(9, H_ / ROWS, B_);   // dy, y-tiles, batch
    dim3 block(256);
    corr_kernel<<<grid, block>>>(in1, in2, out);
}